// round 7
// baseline (speedup 1.0000x reference)
#include <cuda_runtime.h>
#include <cuda_bf16.h>
#include <cstdint>

// ---------------------------------------------------------------------------
// Problem constants
// ---------------------------------------------------------------------------
constexpr int BATCH   = 4;
constexpr int LSEQ    = 8192;       // 64*128 tokens per batch
constexpr int HGRID   = 64, WGRID = 128;
constexpr int DMODEL  = 256;
constexpr int DINNER  = 512;
constexpr int DSTATE  = 64;
constexpr int NHEADS  = 4;
constexpr int HEADDIM = 128;
constexpr int CHUNK   = 128;
constexpr int NCHUNK  = LSEQ / CHUNK;               // 64
constexpr int CONVDIM = DINNER + 2 * DSTATE;        // 640
constexpr int DPROJ   = 2*DINNER + 2*DSTATE + NHEADS; // 1156
constexpr int MROWS   = BATCH * LSEQ;               // 32768

constexpr size_t LF1  = (size_t)MROWS * DMODEL;     // 8.39M
constexpr size_t ZX1  = (size_t)MROWS * DPROJ;      // 37.9M
constexpr size_t XBC1 = (size_t)MROWS * CONVDIM;    // 21.0M
constexpr size_t DT1  = (size_t)MROWS * NHEADS;
constexpr size_t Y1   = (size_t)MROWS * DINNER;     // 16.8M
constexpr size_t ST1  = (size_t)BATCH * NCHUNK * NHEADS * DSTATE * HEADDIM; // 8.39M
constexpr size_t CD1  = (size_t)BATCH * NCHUNK * NHEADS;
constexpr size_t OUT1 = (size_t)MROWS * DMODEL;     // 8.39M

// ---------------------------------------------------------------------------
// Scratch (static device globals: allocation-free kernel_launch)
// ---------------------------------------------------------------------------
__device__ float g_lf  [2 * LF1];
__device__ float g_zx  [2 * ZX1];
__device__ float g_xbcl[XBC1];
__device__ float g_dt  [2 * DT1];
__device__ float g_y   [2 * Y1];
__device__ float g_st  [2 * ST1];
__device__ float g_hp  [2 * ST1];
__device__ float g_cd  [2 * CD1];
__device__ float g_yn  [2 * Y1];

// ---------------------------------------------------------------------------
// 1) Downsample: 4x4 stride-4 conv, writes lf[b][l][c]  (c = tid)
//    64 positions per block; per-thread weight row in registers.
// ---------------------------------------------------------------------------
__global__ __launch_bounds__(256) void down_kernel(
    const float* __restrict__ img, const float* __restrict__ W,
    const float* __restrict__ bias, float* __restrict__ lf)
{
    __shared__ float ps[64 * 48];
    const int tid = threadIdx.x;           // channel 0..255
    const int P0  = blockIdx.x * 64;

    float wr[48];
#pragma unroll
    for (int k = 0; k < 48; k++) wr[k] = W[tid * 48 + k];

#pragma unroll
    for (int w = 0; w < 12; w++) {
        int idx = tid + w * 256;           // < 3072 = 64*48
        int p = idx / 48, k = idx % 48;
        int gp = P0 + p;
        int b = gp >> 13, l = gp & 8191;
        int oy = l >> 7, ox = l & 127;
        int ci = k >> 4, r = k & 15, dy = r >> 2, dx = r & 3;
        ps[idx] = img[(((size_t)(b * 3 + ci) * 256) + oy * 4 + dy) * 512 + ox * 4 + dx];
    }
    __syncthreads();

    const float bz = bias[tid];
    for (int p = 0; p < 64; p++) {
        float acc = bz;
#pragma unroll
        for (int k = 0; k < 48; k++) acc += ps[p * 48 + k] * wr[k];
        int gp = P0 + p;
        int b = gp >> 13, l = gp & 8191;
        lf[((size_t)b * LSEQ + l) * DMODEL + tid] = acc;
    }
}

// ---------------------------------------------------------------------------
// 2) SGEMM: C[M,N] = A[M,K] @ B[N,K]^T.  128x128 tile, BK=8, 8x8/thread.
//    M multiple of 128, K multiple of 8; N guarded.
// ---------------------------------------------------------------------------
__global__ __launch_bounds__(256) void sgemm_nt(
    const float* __restrict__ A, int lda,
    const float* __restrict__ B, int ldb,
    float* __restrict__ C, int ldc, int N, int K)
{
    __shared__ float As[8][128];
    __shared__ float Bs[8][128];
    const int bm = blockIdx.x * 128;
    const int bn = blockIdx.y * 128;
    const int tid = threadIdx.x;
    const int ty = tid >> 4, tx = tid & 15;
    const int lrow = tid >> 1;
    const int lk = (tid & 1) * 4;

    float acc[8][8];
#pragma unroll
    for (int i = 0; i < 8; i++)
#pragma unroll
        for (int j = 0; j < 8; j++) acc[i][j] = 0.f;

    const float* Aptr = A + (size_t)(bm + lrow) * lda + lk;
    const int nrow = bn + lrow;
    const float* Bptr = B + (size_t)nrow * ldb + lk;
    const bool bok = nrow < N;

    for (int k0 = 0; k0 < K; k0 += 8) {
        float4 a4 = *(const float4*)(Aptr + k0);
        float4 b4 = bok ? *(const float4*)(Bptr + k0) : make_float4(0.f, 0.f, 0.f, 0.f);
        As[lk + 0][lrow] = a4.x; As[lk + 1][lrow] = a4.y;
        As[lk + 2][lrow] = a4.z; As[lk + 3][lrow] = a4.w;
        Bs[lk + 0][lrow] = b4.x; Bs[lk + 1][lrow] = b4.y;
        Bs[lk + 2][lrow] = b4.z; Bs[lk + 3][lrow] = b4.w;
        __syncthreads();
#pragma unroll
        for (int k = 0; k < 8; k++) {
            float ar[8], br[8];
            *(float4*)(ar)     = *(const float4*)&As[k][ty * 8];
            *(float4*)(ar + 4) = *(const float4*)&As[k][ty * 8 + 4];
            *(float4*)(br)     = *(const float4*)&Bs[k][tx * 8];
            *(float4*)(br + 4) = *(const float4*)&Bs[k][tx * 8 + 4];
#pragma unroll
            for (int i = 0; i < 8; i++)
#pragma unroll
                for (int j = 0; j < 8; j++)
                    acc[i][j] = fmaf(ar[i], br[j], acc[i][j]);
        }
        __syncthreads();
    }
#pragma unroll
    for (int i = 0; i < 8; i++) {
        float* Crow = C + (size_t)(bm + ty * 8 + i) * ldc + bn + tx * 8;
#pragma unroll
        for (int j = 0; j < 8; j++)
            if (bn + tx * 8 + j < N) Crow[j] = acc[i][j];
    }
}

// ---------------------------------------------------------------------------
// 3) dt = softplus(zx[...,1152+h] + dt_bias[h])
// ---------------------------------------------------------------------------
__global__ __launch_bounds__(256) void dt_kernel(
    const float* __restrict__ zx, const float* __restrict__ dtb,
    float* __restrict__ dt)
{
    int idx = blockIdx.x * 256 + threadIdx.x;
    if (idx >= MROWS * NHEADS) return;
    int h = idx & 3, row = idx >> 2;
    float x = zx[(size_t)row * DPROJ + 2 * DINNER + 2 * DSTATE + h] + dtb[h];
    dt[idx] = (x > 20.f) ? x : log1pf(expf(x));
}

// ---------------------------------------------------------------------------
// 4) Depthwise causal conv1d (K=4) + bias + silu, on xBCl only.
// ---------------------------------------------------------------------------
__global__ __launch_bounds__(256) void conv1d_kernel(
    const float* __restrict__ zx, const float* __restrict__ w,
    const float* __restrict__ bias, float* __restrict__ out)
{
    int gid = blockIdx.x * 256 + threadIdx.x;
    if (gid >= MROWS * CONVDIM) return;
    int ch = gid % CONVDIM;
    int t  = gid / CONVDIM;          // b*L + l
    int l  = t & (LSEQ - 1);
    float acc = bias[ch];
    const float w0 = w[ch * 4 + 0], w1 = w[ch * 4 + 1];
    const float w2 = w[ch * 4 + 2], w3 = w[ch * 4 + 3];
    const float* base = zx + (size_t)t * DPROJ + DINNER + ch;
    if (l >= 3) acc += w0 * base[-(ptrdiff_t)(3 * DPROJ)];
    if (l >= 2) acc += w1 * base[-(ptrdiff_t)(2 * DPROJ)];
    if (l >= 1) acc += w2 * base[-(ptrdiff_t)(1 * DPROJ)];
    acc += w3 * base[0];
    out[gid] = acc / (1.f + __expf(-acc));
}

// ---------------------------------------------------------------------------
// 5) SSD intra-chunk kernel: one block per (b, chunk, head).
//    smem: xs[128][128], Cts[64][132], Bts[64][132], scs[128][128],
//          dts[128], cum[128], ee[128]  -> 200192 bytes dynamic.
// ---------------------------------------------------------------------------
constexpr int SSD_SMEM = (128 * 128 + 2 * 64 * 132 + 128 * 128 + 3 * 128) * 4;

__global__ __launch_bounds__(256, 1) void ssd_chunk_kernel(
    const float* __restrict__ xg, int sx,
    const float* __restrict__ Bg, int sb,
    const float* __restrict__ Cg, int scg,
    const float* __restrict__ dtg,
    const float* __restrict__ A_log,
    const float* __restrict__ Dp,
    float* __restrict__ yout,
    float* __restrict__ states,
    float* __restrict__ cd)
{
    extern __shared__ float sm[];
    float* xs  = sm;                       // 128*128
    float* Cts = xs + 128 * 128;           // 64*132
    float* Bts = Cts + 64 * 132;           // 64*132
    float* scs = Bts + 64 * 132;           // 128*128
    float* dts = scs + 128 * 128;          // 128
    float* cum = dts + 128;                // 128
    float* ee  = cum + 128;                // 128

    const int blk = blockIdx.x;            // ((b*64 + c)*4 + h)
    const int h = blk & 3;
    const int c = (blk >> 2) & 63;
    const int b = blk >> 8;
    const int l0 = b * LSEQ + c * CHUNK;
    const int tid = threadIdx.x;

    if (tid < 128) dts[tid] = dtg[(size_t)(l0 + tid) * NHEADS + h];
#pragma unroll
    for (int w = 0; w < 64; w++) {
        int idx = tid + w * 256;
        int j = idx >> 7, p = idx & 127;
        xs[idx] = xg[(size_t)(l0 + j) * sx + h * HEADDIM + p];
    }
#pragma unroll
    for (int w = 0; w < 32; w++) {
        int idx = tid + w * 256;
        int j = idx >> 6, n = idx & 63;
        Bts[n * 132 + j] = Bg[(size_t)(l0 + j) * sb + n];
        Cts[n * 132 + j] = Cg[(size_t)(l0 + j) * scg + n];
    }
    __syncthreads();

    // serial cumsum by thread 0 (overlapped with CB phase on other threads)
    if (tid == 0) {
        float Ah = -expf(A_log[h]);
        float run = 0.f;
        for (int j = 0; j < 128; j++) { run = fmaf(dts[j], Ah, run); cum[j] = run; }
    }

    // CB phase: CB[i][j] = sum_n C[i][n] * B[j][n]
    const int ty = tid >> 4, tx = tid & 15;
    const int i0 = ty * 8, j0 = tx * 8;
    float acc[8][8];
#pragma unroll
    for (int i = 0; i < 8; i++)
#pragma unroll
        for (int j = 0; j < 8; j++) acc[i][j] = 0.f;

#pragma unroll 4
    for (int n = 0; n < 64; n++) {
        float cr[8], br[8];
        *(float4*)(cr)     = *(const float4*)&Cts[n * 132 + i0];
        *(float4*)(cr + 4) = *(const float4*)&Cts[n * 132 + i0 + 4];
        *(float4*)(br)     = *(const float4*)&Bts[n * 132 + j0];
        *(float4*)(br + 4) = *(const float4*)&Bts[n * 132 + j0 + 4];
#pragma unroll
        for (int i = 0; i < 8; i++)
#pragma unroll
            for (int j = 0; j < 8; j++)
                acc[i][j] = fmaf(cr[i], br[j], acc[i][j]);
    }
    __syncthreads();   // cum ready

    if (tid < 128) ee[tid] = dts[tid] * __expf(cum[127] - cum[tid]);

    // scores = CB * exp(cum_i - cum_j) * dt_j  (j <= i), else 0
    {
        float ci[8], cj[8], dj[8];
#pragma unroll
        for (int r = 0; r < 8; r++) ci[r] = cum[i0 + r];
#pragma unroll
        for (int jj = 0; jj < 8; jj++) { cj[jj] = cum[j0 + jj]; dj[jj] = dts[j0 + jj]; }
#pragma unroll
        for (int r = 0; r < 8; r++) {
            float tmp[8];
#pragma unroll
            for (int jj = 0; jj < 8; jj++) {
                tmp[jj] = (j0 + jj <= i0 + r)
                        ? acc[r][jj] * __expf(ci[r] - cj[jj]) * dj[jj] : 0.f;
            }
            *(float4*)&scs[(i0 + r) * 128 + j0]     = *(float4*)tmp;
            *(float4*)&scs[(i0 + r) * 128 + j0 + 4] = *(float4*)(tmp + 4);
        }
    }
    __syncthreads();   // scs + ee ready

    // y GEMM: y[i][p] = sum_{j<=i} scores[i][j] * x[j][p]   (p0 = tx*8)
    const int p0 = tx * 8;
    float yacc[8][8];
#pragma unroll
    for (int i = 0; i < 8; i++)
#pragma unroll
        for (int j = 0; j < 8; j++) yacc[i][j] = 0.f;

    const int jend = i0 + 8;   // triangular: rows i0..i0+7 need j <= i0+7
    for (int j = 0; j < jend; j++) {
        float sr[8], x8[8];
#pragma unroll
        for (int r = 0; r < 8; r++) sr[r] = scs[(i0 + r) * 128 + j];
        *(float4*)(x8)     = *(const float4*)&xs[j * 128 + p0];
        *(float4*)(x8 + 4) = *(const float4*)&xs[j * 128 + p0 + 4];
#pragma unroll
        for (int r = 0; r < 8; r++)
#pragma unroll
            for (int q = 0; q < 8; q++)
                yacc[r][q] = fmaf(sr[r], x8[q], yacc[r][q]);
    }

    // + D*x, store y (intra-chunk part)
    const float Dh = Dp[h];
#pragma unroll
    for (int r = 0; r < 8; r++) {
        float4 xa = *(const float4*)&xs[(i0 + r) * 128 + p0];
        float4 xb = *(const float4*)&xs[(i0 + r) * 128 + p0 + 4];
        float4 v0, v1;
        v0.x = yacc[r][0] + Dh * xa.x; v0.y = yacc[r][1] + Dh * xa.y;
        v0.z = yacc[r][2] + Dh * xa.z; v0.w = yacc[r][3] + Dh * xa.w;
        v1.x = yacc[r][4] + Dh * xb.x; v1.y = yacc[r][5] + Dh * xb.y;
        v1.z = yacc[r][6] + Dh * xb.z; v1.w = yacc[r][7] + Dh * xb.w;
        float* yp = yout + (size_t)(l0 + i0 + r) * DINNER + h * HEADDIM + p0;
        *(float4*)yp = v0;
        *(float4*)(yp + 4) = v1;
    }

    // states GEMM: states[n][p] = sum_j B[j][n]*dt[j]*exp(cumEnd-cum[j]) * x[j][p]
    const int n0 = ty * 4;
    float sacc[4][8];
#pragma unroll
    for (int i = 0; i < 4; i++)
#pragma unroll
        for (int j = 0; j < 8; j++) sacc[i][j] = 0.f;

    for (int j = 0; j < 128; j++) {
        float ej = ee[j];
        float br[4], x8[8];
#pragma unroll
        for (int r = 0; r < 4; r++) br[r] = Bts[(n0 + r) * 132 + j] * ej;
        *(float4*)(x8)     = *(const float4*)&xs[j * 128 + p0];
        *(float4*)(x8 + 4) = *(const float4*)&xs[j * 128 + p0 + 4];
#pragma unroll
        for (int r = 0; r < 4; r++)
#pragma unroll
            for (int q = 0; q < 8; q++)
                sacc[r][q] = fmaf(br[r], x8[q], sacc[r][q]);
    }
    const size_t sbase = (size_t)blk * (DSTATE * HEADDIM);
#pragma unroll
    for (int r = 0; r < 4; r++) {
        float* sp = states + sbase + (n0 + r) * 128 + p0;
        *(float4*)sp       = *(float4*)&sacc[r][0];
        *(float4*)(sp + 4) = *(float4*)&sacc[r][4];
    }
    if (tid == 0) cd[blk] = __expf(cum[127]);
}

// ---------------------------------------------------------------------------
// 6) Cross-chunk scan: one block per (b,h); 64 sequential chunks.
//    hprev[c] = state BEFORE chunk c.
// ---------------------------------------------------------------------------
__global__ __launch_bounds__(256) void scan_kernel(
    const float* __restrict__ states, const float* __restrict__ cd,
    float* __restrict__ hprev)
{
    const int b = blockIdx.x >> 2, h = blockIdx.x & 3;
    const int tid = threadIdx.x;
    float S[32];
#pragma unroll
    for (int k = 0; k < 32; k++) S[k] = 0.f;
    for (int c = 0; c < NCHUNK; c++) {
        const int blk = (b * NCHUNK + c) * NHEADS + h;
        const size_t base = (size_t)blk * (DSTATE * HEADDIM);
        const float dec = cd[blk];
#pragma unroll
        for (int k = 0; k < 32; k++) {
            int idx = tid + k * 256;
            hprev[base + idx] = S[k];
            S[k] = fmaf(S[k], dec, states[base + idx]);
        }
    }
}

// ---------------------------------------------------------------------------
// 7) Inter-chunk y correction: y[i][p] += exp(cum[i]) * sum_n C[i][n]*hprev[n][p]
// ---------------------------------------------------------------------------
constexpr int YC_SMEM = (128 * 64 + 64 * 128 + 3 * 128) * 4;

__global__ __launch_bounds__(256, 2) void ychunk_kernel(
    const float* __restrict__ Cg, int scg,
    const float* __restrict__ dtg,
    const float* __restrict__ A_log,
    const float* __restrict__ hprev,
    float* __restrict__ y)
{
    extern __shared__ float sm[];
    float* Cs  = sm;             // [128][64]
    float* Ht  = Cs + 128 * 64;  // [64][128]
    float* dts = Ht + 64 * 128;  // 128
    float* cum = dts + 128;      // 128
    float* ex  = cum + 128;      // 128

    const int blk = blockIdx.x;
    const int h = blk & 3;
    const int c = (blk >> 2) & 63;
    const int b = blk >> 8;
    const int l0 = b * LSEQ + c * CHUNK;
    const int tid = threadIdx.x;

    if (tid < 128) dts[tid] = dtg[(size_t)(l0 + tid) * NHEADS + h];
    const size_t hbase = (size_t)blk * (DSTATE * HEADDIM);
#pragma unroll
    for (int w = 0; w < 32; w++) {
        int idx = tid + w * 256;
        int i = idx >> 6, n = idx & 63;
        Cs[idx] = Cg[(size_t)(l0 + i) * scg + n];
        Ht[idx] = hprev[hbase + idx];
    }
    __syncthreads();

    if (tid == 0) {
        float Ah = -expf(A_log[h]);
        float run = 0.f;
        for (int j = 0; j < 128; j++) { run = fmaf(dts[j], Ah, run); cum[j] = run; }
    }

    const int ty = tid >> 4, tx = tid & 15;
    const int i0 = ty * 8, p0 = tx * 8;
    float acc[8][8];
#pragma unroll
    for (int i = 0; i < 8; i++)
#pragma unroll
        for (int j = 0; j < 8; j++) acc[i][j] = 0.f;

#pragma unroll 4
    for (int n = 0; n < 64; n++) {
        float cr[8], h8[8];
#pragma unroll
        for (int r = 0; r < 8; r++) cr[r] = Cs[(i0 + r) * 64 + n];
        *(float4*)(h8)     = *(const float4*)&Ht[n * 128 + p0];
        *(float4*)(h8 + 4) = *(const float4*)&Ht[n * 128 + p0 + 4];
#pragma unroll
        for (int r = 0; r < 8; r++)
#pragma unroll
            for (int q = 0; q < 8; q++)
                acc[r][q] = fmaf(cr[r], h8[q], acc[r][q]);
    }
    __syncthreads();   // cum ready
    if (tid < 128) ex[tid] = __expf(cum[tid]);
    __syncthreads();

#pragma unroll
    for (int r = 0; r < 8; r++) {
        float ei = ex[i0 + r];
        float* yp = y + (size_t)(l0 + i0 + r) * DINNER + h * HEADDIM + p0;
        float4 v = *(float4*)yp;
        v.x += ei * acc[r][0]; v.y += ei * acc[r][1];
        v.z += ei * acc[r][2]; v.w += ei * acc[r][3];
        *(float4*)yp = v;
        v = *(float4*)(yp + 4);
        v.x += ei * acc[r][4]; v.y += ei * acc[r][5];
        v.z += ei * acc[r][6]; v.w += ei * acc[r][7];
        *(float4*)(yp + 4) = v;
    }
}

// ---------------------------------------------------------------------------
// 8) Gated RMSNorm: yn = (y*silu(z)) * rsqrt(mean sq + 1e-5) * norm_w
// ---------------------------------------------------------------------------
__global__ __launch_bounds__(256) void rmsnorm_kernel(
    const float* __restrict__ y, const float* __restrict__ z, int sz,
    const float* __restrict__ nw, float* __restrict__ out)
{
    __shared__ float red[8];
    const int row = blockIdx.x;
    const float* yr = y + (size_t)row * DINNER;
    const float* zr = z + (size_t)row * sz;
    const int tid = threadIdx.x;

    float yv = yr[tid], zv = zr[tid];
    float g0 = yv * (zv / (1.f + __expf(-zv)));
    yv = yr[tid + 256]; zv = zr[tid + 256];
    float g1 = yv * (zv / (1.f + __expf(-zv)));
    float ss = g0 * g0 + g1 * g1;

#pragma unroll
    for (int o = 16; o; o >>= 1) ss += __shfl_xor_sync(~0u, ss, o);
    if ((tid & 31) == 0) red[tid >> 5] = ss;
    __syncthreads();
    if (tid < 8) {
        float v = red[tid];
#pragma unroll
        for (int o = 4; o; o >>= 1) v += __shfl_xor_sync(0xffu, v, o);
        if (tid == 0) red[0] = v;
    }
    __syncthreads();
    const float scale = rsqrtf(red[0] * (1.f / 512.f) + 1e-5f);
    out[(size_t)row * DINNER + tid]       = g0 * scale * nw[tid];
    out[(size_t)row * DINNER + tid + 256] = g1 * scale * nw[tid + 256];
}

// ---------------------------------------------------------------------------
// Host launcher
// ---------------------------------------------------------------------------
extern "C" void kernel_launch(void* const* d_in, const int* in_sizes, int n_in,
                              void* d_out, int out_size)
{
    const float* left  = (const float*)d_in[0];
    const float* right = (const float*)d_in[1];
    const float* dw    = (const float*)d_in[2];
    const float* db    = (const float*)d_in[3];
    const float* inw   = (const float*)d_in[4];
    const float* cw    = (const float*)d_in[5];
    const float* cb    = (const float*)d_in[6];
    const float* dtb   = (const float*)d_in[7];
    const float* Alog  = (const float*)d_in[8];
    const float* Dp    = (const float*)d_in[9];
    const float* nw    = (const float*)d_in[10];
    const float* ow    = (const float*)d_in[11];
    float* out = (float*)d_out;
    (void)in_sizes; (void)n_in; (void)out_size;

    float *lf, *zx, *xbcl, *dt, *y, *st, *hp, *cd, *yn;
    cudaGetSymbolAddress((void**)&lf,   g_lf);
    cudaGetSymbolAddress((void**)&zx,   g_zx);
    cudaGetSymbolAddress((void**)&xbcl, g_xbcl);
    cudaGetSymbolAddress((void**)&dt,   g_dt);
    cudaGetSymbolAddress((void**)&y,    g_y);
    cudaGetSymbolAddress((void**)&st,   g_st);
    cudaGetSymbolAddress((void**)&hp,   g_hp);
    cudaGetSymbolAddress((void**)&cd,   g_cd);
    cudaGetSymbolAddress((void**)&yn,   g_yn);

    cudaFuncSetAttribute(ssd_chunk_kernel,
                         cudaFuncAttributeMaxDynamicSharedMemorySize, SSD_SMEM);
    cudaFuncSetAttribute(ychunk_kernel,
                         cudaFuncAttributeMaxDynamicSharedMemorySize, YC_SMEM);

    // 1) downsample both images -> lf (b,L,256)
    down_kernel<<<512, 256>>>(left,  dw, db, lf);
    down_kernel<<<512, 256>>>(right, dw, db, lf + LF1);

    // 2) in_proj: zx = lf @ in_proj_w^T  (M=32768, N=1156, K=256)
    dim3 gin(MROWS / 128, (DPROJ + 127) / 128);
    sgemm_nt<<<gin, 256>>>(lf,       DMODEL, inw, DMODEL, zx,       DPROJ, DPROJ, DMODEL);
    sgemm_nt<<<gin, 256>>>(lf + LF1, DMODEL, inw, DMODEL, zx + ZX1, DPROJ, DPROJ, DMODEL);

    // 3) dt = softplus(raw + bias)
    dt_kernel<<<(MROWS * NHEADS) / 256, 256>>>(zx,       dtb, dt);
    dt_kernel<<<(MROWS * NHEADS) / 256, 256>>>(zx + ZX1, dtb, dt + DT1);

    // 4) causal depthwise conv + silu on xBCl ONLY (reference asymmetry)
    conv1d_kernel<<<(MROWS * CONVDIM) / 256, 256>>>(zx, cw, cb, xbcl);

    // 5) SSD intra-chunk.
    //    dir0 (yl): x = xr(raw), B = Br(raw), C = Cl(conv), dt = dtl
    //    dir1 (yr): x = xl(conv), B = Bl(conv), C = Cr(raw), dt = dtr
    float* zxr = zx + ZX1;
    ssd_chunk_kernel<<<1024, 256, SSD_SMEM>>>(
        zxr + DINNER, DPROJ, zxr + 2 * DINNER, DPROJ,
        xbcl + DINNER + DSTATE, CONVDIM,
        dt, Alog, Dp, y, st, cd);
    ssd_chunk_kernel<<<1024, 256, SSD_SMEM>>>(
        xbcl, CONVDIM, xbcl + DINNER, CONVDIM,
        zxr + 2 * DINNER + DSTATE, DPROJ,
        dt + DT1, Alog, Dp, y + Y1, st + ST1, cd + CD1);

    // 6) cross-chunk scan
    scan_kernel<<<16, 256>>>(st,       cd,       hp);
    scan_kernel<<<16, 256>>>(st + ST1, cd + CD1, hp + ST1);

    // 7) inter-chunk correction
    ychunk_kernel<<<1024, 256, YC_SMEM>>>(
        xbcl + DINNER + DSTATE, CONVDIM, dt, Alog, hp, y);
    ychunk_kernel<<<1024, 256, YC_SMEM>>>(
        zxr + 2 * DINNER + DSTATE, DPROJ, dt + DT1, Alog, hp + ST1, y + Y1);

    // 8) gated rmsnorm (zl with yl, zr with yr)
    rmsnorm_kernel<<<MROWS, 256>>>(y,      zx,       DPROJ, nw, yn);
    rmsnorm_kernel<<<MROWS, 256>>>(y + Y1, zx + ZX1, DPROJ, nw, yn + Y1);

    // 9) out_proj: out = yn @ out_proj_w^T  (M=32768, N=256, K=512)
    dim3 gout(MROWS / 128, DMODEL / 128);
    sgemm_nt<<<gout, 256>>>(yn,      DINNER, ow, DINNER, out,        DMODEL, DMODEL, DINNER);
    sgemm_nt<<<gout, 256>>>(yn + Y1, DINNER, ow, DINNER, out + OUT1, DMODEL, DMODEL, DINNER);
}

// round 16
// speedup vs baseline: 1.4771x; 1.4771x over previous
#include <cuda_runtime.h>
#include <cuda_bf16.h>
#include <cstdint>

// ---------------------------------------------------------------------------
// Problem constants
// ---------------------------------------------------------------------------
constexpr int BATCH   = 4;
constexpr int LSEQ    = 8192;
constexpr int DMODEL  = 256;
constexpr int DINNER  = 512;
constexpr int DSTATE  = 64;
constexpr int NHEADS  = 4;
constexpr int HEADDIM = 128;
constexpr int CHUNK   = 128;
constexpr int NCHUNK  = LSEQ / CHUNK;                 // 64
constexpr int CONVDIM = DINNER + 2 * DSTATE;          // 640
constexpr int DPROJ   = 2*DINNER + 2*DSTATE + NHEADS; // 1156
constexpr int MROWS   = BATCH * LSEQ;                 // 32768

constexpr int KIN3  = 3 * DMODEL;   // 768  (bf16x3 K for in_proj)
constexpr int KOUT3 = 3 * DINNER;   // 1536 (bf16x3 K for out_proj)

constexpr size_t ZX1  = (size_t)MROWS * DPROJ;
constexpr size_t DT1  = (size_t)MROWS * NHEADS;
constexpr size_t XBC1 = (size_t)MROWS * CONVDIM;
constexpr size_t Y1   = (size_t)MROWS * DINNER;
constexpr size_t ST1  = (size_t)BATCH * NCHUNK * NHEADS * DSTATE * HEADDIM;
constexpr size_t CD1  = (size_t)BATCH * NCHUNK * NHEADS;
constexpr size_t OUT1 = (size_t)MROWS * DMODEL;
constexpr size_t AB1  = (size_t)MROWS * KIN3;
constexpr size_t YB1  = (size_t)MROWS * KOUT3;

// ---------------------------------------------------------------------------
// Scratch (static device globals)
// ---------------------------------------------------------------------------
__device__ float g_zx  [2 * ZX1];
__device__ float g_xbcl[XBC1];
__device__ float g_dt  [2 * DT1];
__device__ float g_y   [2 * Y1];
__device__ float g_st  [2 * ST1];
__device__ float g_hp  [2 * ST1];
__device__ float g_cd  [2 * CD1];
__device__ __nv_bfloat16 g_ab [2 * AB1];                 // [Ah | Al | Ah]
__device__ __nv_bfloat16 g_ynb[2 * YB1];                 // [Ah | Al | Ah]
__device__ __nv_bfloat16 g_wib[(size_t)DPROJ  * KIN3 ];  // [Bh | Bh | Bl]
__device__ __nv_bfloat16 g_wob[(size_t)DMODEL * KOUT3];  // [Bh | Bh | Bl]

// ---------------------------------------------------------------------------
// Helpers
// ---------------------------------------------------------------------------
__device__ __forceinline__ uint32_t smem_u32(const void* p) {
    uint32_t a;
    asm("{ .reg .u64 t; cvta.to.shared.u64 t, %1; cvt.u32.u64 %0, t; }"
        : "=r"(a) : "l"(p));
    return a;
}
__device__ __forceinline__ void cp_async16(uint32_t dst, const void* src, int sz) {
    asm volatile("cp.async.cg.shared.global [%0], [%1], 16, %2;"
                 :: "r"(dst), "l"(src), "r"(sz) : "memory");
}
__device__ __forceinline__ void ldsm4(uint32_t* r, uint32_t a) {
    asm volatile("ldmatrix.sync.aligned.m8n8.x4.shared.b16 {%0,%1,%2,%3}, [%4];"
                 : "=r"(r[0]), "=r"(r[1]), "=r"(r[2]), "=r"(r[3]) : "r"(a));
}
__device__ __forceinline__ void mma16816(float* d, const uint32_t* a, const uint32_t* b) {
    asm volatile(
        "mma.sync.aligned.m16n8k16.row.col.f32.bf16.bf16.f32 "
        "{%0,%1,%2,%3}, {%4,%5,%6,%7}, {%8,%9}, {%0,%1,%2,%3};"
        : "+f"(d[0]), "+f"(d[1]), "+f"(d[2]), "+f"(d[3])
        : "r"(a[0]), "r"(a[1]), "r"(a[2]), "r"(a[3]), "r"(b[0]), "r"(b[1]));
}
__device__ __forceinline__ void bf16split(float x, __nv_bfloat16& h, __nv_bfloat16& l) {
    h = __float2bfloat16(x);
    l = __float2bfloat16(x - __bfloat162float(h));
}

// ---------------------------------------------------------------------------
// 0) Weight split:  W[R,K] fp32 -> out[R, 3K] bf16 as [Bh | Bh | Bl]
// ---------------------------------------------------------------------------
__global__ __launch_bounds__(256) void wsplit_kernel(
    const float* __restrict__ W, __nv_bfloat16* __restrict__ out, int total, int K)
{
    int i = blockIdx.x * 256 + threadIdx.x;
    if (i >= total) return;
    int r = i / K, k = i - r * K;
    __nv_bfloat16 h, l;
    bf16split(W[i], h, l);
    __nv_bfloat16* row = out + (size_t)r * 3 * K;
    row[k] = h; row[K + k] = h; row[2 * K + k] = l;
}

// ---------------------------------------------------------------------------
// 1) Downsample: 4x4 stride-4 conv, writes bf16x3 [Ah|Al|Ah] directly.
// ---------------------------------------------------------------------------
__global__ __launch_bounds__(256) void down_kernel(
    const float* __restrict__ img, const float* __restrict__ W,
    const float* __restrict__ bias, __nv_bfloat16* __restrict__ ab)
{
    __shared__ float ps[64 * 48];
    const int tid = threadIdx.x;           // channel 0..255
    const int P0  = blockIdx.x * 64;

    float wr[48];
#pragma unroll
    for (int k = 0; k < 48; k++) wr[k] = W[tid * 48 + k];

#pragma unroll
    for (int w = 0; w < 12; w++) {
        int idx = tid + w * 256;
        int p = idx / 48, k = idx % 48;
        int gp = P0 + p;
        int b = gp >> 13, l = gp & 8191;
        int oy = l >> 7, ox = l & 127;
        int ci = k >> 4, r = k & 15, dy = r >> 2, dx = r & 3;
        ps[idx] = img[(((size_t)(b * 3 + ci) * 256) + oy * 4 + dy) * 512 + ox * 4 + dx];
    }
    __syncthreads();

    const float bz = bias[tid];
    for (int p = 0; p < 64; p++) {
        float acc = bz;
#pragma unroll
        for (int k = 0; k < 48; k++) acc += ps[p * 48 + k] * wr[k];
        int gp = P0 + p;
        __nv_bfloat16 h, l;
        bf16split(acc, h, l);
        __nv_bfloat16* row = ab + (size_t)gp * KIN3 + tid;
        row[0]          = h;
        row[DMODEL]     = l;
        row[2 * DMODEL] = h;
    }
}

// ---------------------------------------------------------------------------
// 2) bf16 GEMM via mma.sync (HMMA): C[M,N] = A[M,K2] @ B[N,K2]^T, fp32 accum.
//    128x128 tile, BK=32, 8 warps (2x4), 64x32 per warp, cp.async dbl-buffer.
//    Smem rows padded to 40 bf16 (80B) -> ldmatrix conflict-free.
// ---------------------------------------------------------------------------
__global__ __launch_bounds__(256) void gemm_bf16_mma(
    const __nv_bfloat16* __restrict__ A,
    const __nv_bfloat16* __restrict__ B,
    int K2, float* __restrict__ C, int ldc, int Nvalid)
{
    __shared__ __nv_bfloat16 sA[2][128 * 40];
    __shared__ __nv_bfloat16 sB[2][128 * 40];

    const int tid = threadIdx.x, lane = tid & 31, wid = tid >> 5;
    const int m0 = blockIdx.y * 128, n0 = blockIdx.x * 128;
    const int wm = wid & 1, wn = wid >> 1;      // 2 (M) x 4 (N) warp grid
    const int NC = K2 >> 5;                     // BK=32 chunks

    // per-thread load coords: 2 x (row, 16B-col) covering 128 rows x 64B
    const int r0l = tid >> 2, c16 = tid & 3;

    float acc[4][4][4];
#pragma unroll
    for (int mt = 0; mt < 4; mt++)
#pragma unroll
        for (int nt = 0; nt < 4; nt++)
#pragma unroll
            for (int q = 0; q < 4; q++) acc[mt][nt][q] = 0.f;

    // ldmatrix per-lane addresses (element offsets within a tile buffer)
    const int a_row = (lane & 15);
    const int a_col = (lane >> 4) * 8;
    const int b_nof = (lane & 7) + ((lane >> 4) << 3);
    const int b_kof = ((lane >> 3) & 1) * 8;

    auto issue = [&](int c, int s) {
#pragma unroll
        for (int half = 0; half < 2; half++) {
            int r = r0l + half * 64;
            const __nv_bfloat16* srcA = A + (size_t)(m0 + r) * K2 + c * 32 + c16 * 8;
            cp_async16(smem_u32(&sA[s][r * 40 + c16 * 8]), srcA, 16);
            int nr = n0 + r;
            const __nv_bfloat16* srcB = B + (size_t)nr * K2 + c * 32 + c16 * 8;
            cp_async16(smem_u32(&sB[s][r * 40 + c16 * 8]), srcB, nr < Nvalid ? 16 : 0);
        }
        asm volatile("cp.async.commit_group;" ::: "memory");
    };

    issue(0, 0);
    for (int c = 0; c < NC; c++) {
        const int s = c & 1;
        if (c + 1 < NC) {
            issue(c + 1, s ^ 1);
            asm volatile("cp.async.wait_group 1;" ::: "memory");
        } else {
            asm volatile("cp.async.wait_group 0;" ::: "memory");
        }
        __syncthreads();

        const __nv_bfloat16* Ab = sA[s];
        const __nv_bfloat16* Bb = sB[s];
#pragma unroll
        for (int ks = 0; ks < 2; ks++) {
            uint32_t af[4][4];
#pragma unroll
            for (int mt = 0; mt < 4; mt++) {
                int row = wm * 64 + mt * 16 + a_row;
                ldsm4(af[mt], smem_u32(&Ab[row * 40 + ks * 16 + a_col]));
            }
            uint32_t bf[4][2];
#pragma unroll
            for (int np = 0; np < 2; np++) {
                int n = wn * 32 + np * 16 + b_nof;
                uint32_t r4[4];
                ldsm4(r4, smem_u32(&Bb[n * 40 + ks * 16 + b_kof]));
                bf[np * 2][0] = r4[0]; bf[np * 2][1] = r4[1];
                bf[np * 2 + 1][0] = r4[2]; bf[np * 2 + 1][1] = r4[3];
            }
#pragma unroll
            for (int mt = 0; mt < 4; mt++)
#pragma unroll
                for (int nt = 0; nt < 4; nt++)
                    mma16816(acc[mt][nt], af[mt], bf[nt]);
        }
        __syncthreads();
    }

    // epilogue: lane l owns rows (l>>2, l>>2+8), col pair 2*(l&3) of each tile
    const int er = lane >> 2, ec = (lane & 3) * 2;
#pragma unroll
    for (int mt = 0; mt < 4; mt++) {
        int row = m0 + wm * 64 + mt * 16 + er;
#pragma unroll
        for (int nt = 0; nt < 4; nt++) {
            int col = n0 + wn * 32 + nt * 8 + ec;
            if (col < Nvalid) {
                float2 v0 = make_float2(acc[mt][nt][0], acc[mt][nt][1]);
                float2 v1 = make_float2(acc[mt][nt][2], acc[mt][nt][3]);
                *(float2*)(C + (size_t)row * ldc + col) = v0;
                *(float2*)(C + (size_t)(row + 8) * ldc + col) = v1;
            }
        }
    }
}

// ---------------------------------------------------------------------------
// 3) dt = softplus(zx[...,1152+h] + dt_bias[h])
// ---------------------------------------------------------------------------
__global__ __launch_bounds__(256) void dt_kernel(
    const float* __restrict__ zx, const float* __restrict__ dtb,
    float* __restrict__ dt)
{
    int idx = blockIdx.x * 256 + threadIdx.x;
    if (idx >= MROWS * NHEADS) return;
    int h = idx & 3, row = idx >> 2;
    float x = zx[(size_t)row * DPROJ + 2 * DINNER + 2 * DSTATE + h] + dtb[h];
    dt[idx] = (x > 20.f) ? x : log1pf(expf(x));
}

// ---------------------------------------------------------------------------
// 4) Depthwise causal conv1d (K=4) + bias + silu, on xBCl only.
// ---------------------------------------------------------------------------
__global__ __launch_bounds__(256) void conv1d_kernel(
    const float* __restrict__ zx, const float* __restrict__ w,
    const float* __restrict__ bias, float* __restrict__ out)
{
    int gid = blockIdx.x * 256 + threadIdx.x;
    if (gid >= MROWS * CONVDIM) return;
    int ch = gid % CONVDIM;
    int t  = gid / CONVDIM;
    int l  = t & (LSEQ - 1);
    float acc = bias[ch];
    const float w0 = w[ch * 4 + 0], w1 = w[ch * 4 + 1];
    const float w2 = w[ch * 4 + 2], w3 = w[ch * 4 + 3];
    const float* base = zx + (size_t)t * DPROJ + DINNER + ch;
    if (l >= 3) acc += w0 * base[-(ptrdiff_t)(3 * DPROJ)];
    if (l >= 2) acc += w1 * base[-(ptrdiff_t)(2 * DPROJ)];
    if (l >= 1) acc += w2 * base[-(ptrdiff_t)(1 * DPROJ)];
    acc += w3 * base[0];
    out[gid] = acc / (1.f + __expf(-acc));
}

// ---------------------------------------------------------------------------
// 5) SSD intra-chunk kernel: one block per (b, chunk, head).
// ---------------------------------------------------------------------------
constexpr int SSD_SMEM = (128 * 128 + 2 * 64 * 132 + 128 * 128 + 3 * 128) * 4;

__global__ __launch_bounds__(256, 1) void ssd_chunk_kernel(
    const float* __restrict__ xg, int sx,
    const float* __restrict__ Bg, int sb,
    const float* __restrict__ Cg, int scg,
    const float* __restrict__ dtg,
    const float* __restrict__ A_log,
    const float* __restrict__ Dp,
    float* __restrict__ yout,
    float* __restrict__ states,
    float* __restrict__ cd)
{
    extern __shared__ float sm[];
    float* xs  = sm;
    float* Cts = xs + 128 * 128;
    float* Bts = Cts + 64 * 132;
    float* scs = Bts + 64 * 132;
    float* dts = scs + 128 * 128;
    float* cum = dts + 128;
    float* ee  = cum + 128;

    const int blk = blockIdx.x;
    const int h = blk & 3;
    const int c = (blk >> 2) & 63;
    const int b = blk >> 8;
    const int l0 = b * LSEQ + c * CHUNK;
    const int tid = threadIdx.x;

    if (tid < 128) dts[tid] = dtg[(size_t)(l0 + tid) * NHEADS + h];
#pragma unroll
    for (int w = 0; w < 64; w++) {
        int idx = tid + w * 256;
        int j = idx >> 7, p = idx & 127;
        xs[idx] = xg[(size_t)(l0 + j) * sx + h * HEADDIM + p];
    }
#pragma unroll
    for (int w = 0; w < 32; w++) {
        int idx = tid + w * 256;
        int j = idx >> 6, n = idx & 63;
        Bts[n * 132 + j] = Bg[(size_t)(l0 + j) * sb + n];
        Cts[n * 132 + j] = Cg[(size_t)(l0 + j) * scg + n];
    }
    __syncthreads();

    if (tid == 0) {
        float Ah = -expf(A_log[h]);
        float run = 0.f;
        for (int j = 0; j < 128; j++) { run = fmaf(dts[j], Ah, run); cum[j] = run; }
    }

    const int ty = tid >> 4, tx = tid & 15;
    const int i0 = ty * 8, j0 = tx * 8;
    float acc[8][8];
#pragma unroll
    for (int i = 0; i < 8; i++)
#pragma unroll
        for (int j = 0; j < 8; j++) acc[i][j] = 0.f;

#pragma unroll 4
    for (int n = 0; n < 64; n++) {
        float cr[8], br[8];
        *(float4*)(cr)     = *(const float4*)&Cts[n * 132 + i0];
        *(float4*)(cr + 4) = *(const float4*)&Cts[n * 132 + i0 + 4];
        *(float4*)(br)     = *(const float4*)&Bts[n * 132 + j0];
        *(float4*)(br + 4) = *(const float4*)&Bts[n * 132 + j0 + 4];
#pragma unroll
        for (int i = 0; i < 8; i++)
#pragma unroll
            for (int j = 0; j < 8; j++)
                acc[i][j] = fmaf(cr[i], br[j], acc[i][j]);
    }
    __syncthreads();

    if (tid < 128) ee[tid] = dts[tid] * __expf(cum[127] - cum[tid]);

    {
        float ci[8], cj[8], dj[8];
#pragma unroll
        for (int r = 0; r < 8; r++) ci[r] = cum[i0 + r];
#pragma unroll
        for (int jj = 0; jj < 8; jj++) { cj[jj] = cum[j0 + jj]; dj[jj] = dts[j0 + jj]; }
#pragma unroll
        for (int r = 0; r < 8; r++) {
            float tmp[8];
#pragma unroll
            for (int jj = 0; jj < 8; jj++) {
                tmp[jj] = (j0 + jj <= i0 + r)
                        ? acc[r][jj] * __expf(ci[r] - cj[jj]) * dj[jj] : 0.f;
            }
            *(float4*)&scs[(i0 + r) * 128 + j0]     = *(float4*)tmp;
            *(float4*)&scs[(i0 + r) * 128 + j0 + 4] = *(float4*)(tmp + 4);
        }
    }
    __syncthreads();

    const int p0 = tx * 8;
    float yacc[8][8];
#pragma unroll
    for (int i = 0; i < 8; i++)
#pragma unroll
        for (int j = 0; j < 8; j++) yacc[i][j] = 0.f;

    const int jend = i0 + 8;
    for (int j = 0; j < jend; j++) {
        float sr[8], x8[8];
#pragma unroll
        for (int r = 0; r < 8; r++) sr[r] = scs[(i0 + r) * 128 + j];
        *(float4*)(x8)     = *(const float4*)&xs[j * 128 + p0];
        *(float4*)(x8 + 4) = *(const float4*)&xs[j * 128 + p0 + 4];
#pragma unroll
        for (int r = 0; r < 8; r++)
#pragma unroll
            for (int q = 0; q < 8; q++)
                yacc[r][q] = fmaf(sr[r], x8[q], yacc[r][q]);
    }

    const float Dh = Dp[h];
#pragma unroll
    for (int r = 0; r < 8; r++) {
        float4 xa = *(const float4*)&xs[(i0 + r) * 128 + p0];
        float4 xb = *(const float4*)&xs[(i0 + r) * 128 + p0 + 4];
        float4 v0, v1;
        v0.x = yacc[r][0] + Dh * xa.x; v0.y = yacc[r][1] + Dh * xa.y;
        v0.z = yacc[r][2] + Dh * xa.z; v0.w = yacc[r][3] + Dh * xa.w;
        v1.x = yacc[r][4] + Dh * xb.x; v1.y = yacc[r][5] + Dh * xb.y;
        v1.z = yacc[r][6] + Dh * xb.z; v1.w = yacc[r][7] + Dh * xb.w;
        float* yp = yout + (size_t)(l0 + i0 + r) * DINNER + h * HEADDIM + p0;
        *(float4*)yp = v0;
        *(float4*)(yp + 4) = v1;
    }

    const int n0 = ty * 4;
    float sacc[4][8];
#pragma unroll
    for (int i = 0; i < 4; i++)
#pragma unroll
        for (int j = 0; j < 8; j++) sacc[i][j] = 0.f;

    for (int j = 0; j < 128; j++) {
        float ej = ee[j];
        float br[4], x8[8];
#pragma unroll
        for (int r = 0; r < 4; r++) br[r] = Bts[(n0 + r) * 132 + j] * ej;
        *(float4*)(x8)     = *(const float4*)&xs[j * 128 + p0];
        *(float4*)(x8 + 4) = *(const float4*)&xs[j * 128 + p0 + 4];
#pragma unroll
        for (int r = 0; r < 4; r++)
#pragma unroll
            for (int q = 0; q < 8; q++)
                sacc[r][q] = fmaf(br[r], x8[q], sacc[r][q]);
    }
    const size_t sbase = (size_t)blk * (DSTATE * HEADDIM);
#pragma unroll
    for (int r = 0; r < 4; r++) {
        float* sp = states + sbase + (n0 + r) * 128 + p0;
        *(float4*)sp       = *(float4*)&sacc[r][0];
        *(float4*)(sp + 4) = *(float4*)&sacc[r][4];
    }
    if (tid == 0) cd[blk] = __expf(cum[127]);
}

// ---------------------------------------------------------------------------
// 6) Cross-chunk scan
// ---------------------------------------------------------------------------
__global__ __launch_bounds__(256) void scan_kernel(
    const float* __restrict__ states, const float* __restrict__ cd,
    float* __restrict__ hprev)
{
    const int b = blockIdx.x >> 2, h = blockIdx.x & 3;
    const int tid = threadIdx.x;
    float S[32];
#pragma unroll
    for (int k = 0; k < 32; k++) S[k] = 0.f;
    for (int c = 0; c < NCHUNK; c++) {
        const int blk = (b * NCHUNK + c) * NHEADS + h;
        const size_t base = (size_t)blk * (DSTATE * HEADDIM);
        const float dec = cd[blk];
#pragma unroll
        for (int k = 0; k < 32; k++) {
            int idx = tid + k * 256;
            hprev[base + idx] = S[k];
            S[k] = fmaf(S[k], dec, states[base + idx]);
        }
    }
}

// ---------------------------------------------------------------------------
// 7) Inter-chunk y correction
// ---------------------------------------------------------------------------
constexpr int YC_SMEM = (128 * 64 + 64 * 128 + 3 * 128) * 4;

__global__ __launch_bounds__(256, 2) void ychunk_kernel(
    const float* __restrict__ Cg, int scg,
    const float* __restrict__ dtg,
    const float* __restrict__ A_log,
    const float* __restrict__ hprev,
    float* __restrict__ y)
{
    extern __shared__ float sm[];
    float* Cs  = sm;
    float* Ht  = Cs + 128 * 64;
    float* dts = Ht + 64 * 128;
    float* cum = dts + 128;
    float* ex  = cum + 128;

    const int blk = blockIdx.x;
    const int h = blk & 3;
    const int c = (blk >> 2) & 63;
    const int b = blk >> 8;
    const int l0 = b * LSEQ + c * CHUNK;
    const int tid = threadIdx.x;

    if (tid < 128) dts[tid] = dtg[(size_t)(l0 + tid) * NHEADS + h];
    const size_t hbase = (size_t)blk * (DSTATE * HEADDIM);
#pragma unroll
    for (int w = 0; w < 32; w++) {
        int idx = tid + w * 256;
        int i = idx >> 6, n = idx & 63;
        Cs[idx] = Cg[(size_t)(l0 + i) * scg + n];
        Ht[idx] = hprev[hbase + idx];
    }
    __syncthreads();

    if (tid == 0) {
        float Ah = -expf(A_log[h]);
        float run = 0.f;
        for (int j = 0; j < 128; j++) { run = fmaf(dts[j], Ah, run); cum[j] = run; }
    }

    const int ty = tid >> 4, tx = tid & 15;
    const int i0 = ty * 8, p0 = tx * 8;
    float acc[8][8];
#pragma unroll
    for (int i = 0; i < 8; i++)
#pragma unroll
        for (int j = 0; j < 8; j++) acc[i][j] = 0.f;

#pragma unroll 4
    for (int n = 0; n < 64; n++) {
        float cr[8], h8[8];
#pragma unroll
        for (int r = 0; r < 8; r++) cr[r] = Cs[(i0 + r) * 64 + n];
        *(float4*)(h8)     = *(const float4*)&Ht[n * 128 + p0];
        *(float4*)(h8 + 4) = *(const float4*)&Ht[n * 128 + p0 + 4];
#pragma unroll
        for (int r = 0; r < 8; r++)
#pragma unroll
            for (int q = 0; q < 8; q++)
                acc[r][q] = fmaf(cr[r], h8[q], acc[r][q]);
    }
    __syncthreads();
    if (tid < 128) ex[tid] = __expf(cum[tid]);
    __syncthreads();

#pragma unroll
    for (int r = 0; r < 8; r++) {
        float ei = ex[i0 + r];
        float* yp = y + (size_t)(l0 + i0 + r) * DINNER + h * HEADDIM + p0;
        float4 v = *(float4*)yp;
        v.x += ei * acc[r][0]; v.y += ei * acc[r][1];
        v.z += ei * acc[r][2]; v.w += ei * acc[r][3];
        *(float4*)yp = v;
        v = *(float4*)(yp + 4);
        v.x += ei * acc[r][4]; v.y += ei * acc[r][5];
        v.z += ei * acc[r][6]; v.w += ei * acc[r][7];
        *(float4*)(yp + 4) = v;
    }
}

// ---------------------------------------------------------------------------
// 8) Gated RMSNorm -> bf16x3 split output [Ah | Al | Ah]
// ---------------------------------------------------------------------------
__global__ __launch_bounds__(256) void rmsnorm_kernel(
    const float* __restrict__ y, const float* __restrict__ z, int sz,
    const float* __restrict__ nw, __nv_bfloat16* __restrict__ out)
{
    __shared__ float red[8];
    const int row = blockIdx.x;
    const float* yr = y + (size_t)row * DINNER;
    const float* zr = z + (size_t)row * sz;
    const int tid = threadIdx.x;

    float yv = yr[tid], zv = zr[tid];
    float g0 = yv * (zv / (1.f + __expf(-zv)));
    yv = yr[tid + 256]; zv = zr[tid + 256];
    float g1 = yv * (zv / (1.f + __expf(-zv)));
    float ss = g0 * g0 + g1 * g1;

#pragma unroll
    for (int o = 16; o; o >>= 1) ss += __shfl_xor_sync(~0u, ss, o);
    if ((tid & 31) == 0) red[tid >> 5] = ss;
    __syncthreads();
    if (tid < 8) {
        float v = red[tid];
#pragma unroll
        for (int o = 4; o; o >>= 1) v += __shfl_xor_sync(0xffu, v, o);
        if (tid == 0) red[0] = v;
    }
    __syncthreads();
    const float scale = rsqrtf(red[0] * (1.f / 512.f) + 1e-5f);
    float v0 = g0 * scale * nw[tid];
    float v1 = g1 * scale * nw[tid + 256];
    __nv_bfloat16 h, l;
    __nv_bfloat16* rowp = out + (size_t)row * KOUT3;
    bf16split(v0, h, l);
    rowp[tid] = h; rowp[DINNER + tid] = l; rowp[2 * DINNER + tid] = h;
    bf16split(v1, h, l);
    rowp[tid + 256] = h; rowp[DINNER + tid + 256] = l; rowp[2 * DINNER + tid + 256] = h;
}

// ---------------------------------------------------------------------------
// Host launcher
// ---------------------------------------------------------------------------
extern "C" void kernel_launch(void* const* d_in, const int* in_sizes, int n_in,
                              void* d_out, int out_size)
{
    const float* left  = (const float*)d_in[0];
    const float* right = (const float*)d_in[1];
    const float* dw    = (const float*)d_in[2];
    const float* db    = (const float*)d_in[3];
    const float* inw   = (const float*)d_in[4];
    const float* cw    = (const float*)d_in[5];
    const float* cb    = (const float*)d_in[6];
    const float* dtb   = (const float*)d_in[7];
    const float* Alog  = (const float*)d_in[8];
    const float* Dp    = (const float*)d_in[9];
    const float* nw    = (const float*)d_in[10];
    const float* ow    = (const float*)d_in[11];
    float* out = (float*)d_out;
    (void)in_sizes; (void)n_in; (void)out_size;

    float *zx, *xbcl, *dt, *y, *st, *hp, *cd;
    __nv_bfloat16 *ab, *ynb, *wib, *wob;
    cudaGetSymbolAddress((void**)&zx,   g_zx);
    cudaGetSymbolAddress((void**)&xbcl, g_xbcl);
    cudaGetSymbolAddress((void**)&dt,   g_dt);
    cudaGetSymbolAddress((void**)&y,    g_y);
    cudaGetSymbolAddress((void**)&st,   g_st);
    cudaGetSymbolAddress((void**)&hp,   g_hp);
    cudaGetSymbolAddress((void**)&cd,   g_cd);
    cudaGetSymbolAddress((void**)&ab,   g_ab);
    cudaGetSymbolAddress((void**)&ynb,  g_ynb);
    cudaGetSymbolAddress((void**)&wib,  g_wib);
    cudaGetSymbolAddress((void**)&wob,  g_wob);

    cudaFuncSetAttribute(ssd_chunk_kernel,
                         cudaFuncAttributeMaxDynamicSharedMemorySize, SSD_SMEM);
    cudaFuncSetAttribute(ychunk_kernel,
                         cudaFuncAttributeMaxDynamicSharedMemorySize, YC_SMEM);

    // 0) weight splits (bf16x3 [h|h|l])
    wsplit_kernel<<<(DPROJ * DMODEL + 255) / 256, 256>>>(inw, wib, DPROJ * DMODEL, DMODEL);
    wsplit_kernel<<<(DMODEL * DINNER + 255) / 256, 256>>>(ow,  wob, DMODEL * DINNER, DINNER);

    // 1) downsample both images -> bf16x3 activations
    down_kernel<<<512, 256>>>(left,  dw, db, ab);
    down_kernel<<<512, 256>>>(right, dw, db, ab + AB1);

    // 2) in_proj via HMMA bf16x3 (K2=768)
    {
        dim3 g((DPROJ + 127) / 128, MROWS / 128);
        gemm_bf16_mma<<<g, 256>>>(ab,       wib, KIN3, zx,       DPROJ, DPROJ);
        gemm_bf16_mma<<<g, 256>>>(ab + AB1, wib, KIN3, zx + ZX1, DPROJ, DPROJ);
    }

    // 3) dt = softplus(raw + bias)
    dt_kernel<<<(MROWS * NHEADS) / 256, 256>>>(zx,       dtb, dt);
    dt_kernel<<<(MROWS * NHEADS) / 256, 256>>>(zx + ZX1, dtb, dt + DT1);

    // 4) causal depthwise conv + silu on xBCl ONLY
    conv1d_kernel<<<(MROWS * CONVDIM) / 256, 256>>>(zx, cw, cb, xbcl);

    // 5) SSD intra-chunk (cross-wired as in reference)
    float* zxr = zx + ZX1;
    ssd_chunk_kernel<<<1024, 256, SSD_SMEM>>>(
        zxr + DINNER, DPROJ, zxr + 2 * DINNER, DPROJ,
        xbcl + DINNER + DSTATE, CONVDIM,
        dt, Alog, Dp, y, st, cd);
    ssd_chunk_kernel<<<1024, 256, SSD_SMEM>>>(
        xbcl, CONVDIM, xbcl + DINNER, CONVDIM,
        zxr + 2 * DINNER + DSTATE, DPROJ,
        dt + DT1, Alog, Dp, y + Y1, st + ST1, cd + CD1);

    // 6) cross-chunk scan
    scan_kernel<<<16, 256>>>(st,       cd,       hp);
    scan_kernel<<<16, 256>>>(st + ST1, cd + CD1, hp + ST1);

    // 7) inter-chunk correction
    ychunk_kernel<<<1024, 256, YC_SMEM>>>(
        xbcl + DINNER + DSTATE, CONVDIM, dt, Alog, hp, y);
    ychunk_kernel<<<1024, 256, YC_SMEM>>>(
        zxr + 2 * DINNER + DSTATE, DPROJ, dt + DT1, Alog, hp + ST1, y + Y1);

    // 8) gated rmsnorm -> bf16x3 activations for out_proj
    rmsnorm_kernel<<<MROWS, 256>>>(y,      zx,       DPROJ, nw, ynb);
    rmsnorm_kernel<<<MROWS, 256>>>(y + Y1, zx + ZX1, DPROJ, nw, ynb + YB1);

    // 9) out_proj via HMMA bf16x3 (K2=1536)
    {
        dim3 g(DMODEL / 128, MROWS / 128);
        gemm_bf16_mma<<<g, 256>>>(ynb,       wob, KOUT3, out,        DMODEL, DMODEL);
        gemm_bf16_mma<<<g, 256>>>(ynb + YB1, wob, KOUT3, out + OUT1, DMODEL, DMODEL);
    }
}